// round 11
// baseline (speedup 1.0000x reference)
#include <cuda_runtime.h>
#include <cuda_fp16.h>
#include <cstdint>

#define S_LEN 4096
#define EMB   1024
#define HALF  512
#define NHEAD 16
#define DH    32
#define SPLIT 4
#define KEYS_PER_SPLIT (S_LEN / SPLIT)

// f16 scratch
__device__ __half g_xh [S_LEN * HALF];   // x left half
__device__ __half g_wh [2560 * HALF];    // Wq|Wk|Wv|Wo rows (k-major)
__device__ __half g_qh [S_LEN * HALF];   // Q (scale*log2e folded in)
__device__ __half g_kh [S_LEN * HALF];
__device__ __half g_vh [S_LEN * HALF];
__device__ __half g_ath[S_LEN * HALF];   // attention output (f16)

// split-K partials (fp32)
__device__ float g_po[SPLIT][S_LEN * HALF];
__device__ float g_pl[SPLIT][S_LEN * NHEAD];

__device__ __forceinline__ uint32_t packh2(float lo, float hi) {
    uint32_t r;
    asm("cvt.rn.f16x2.f32 %0, %1, %2;" : "=r"(r) : "f"(hi), "f"(lo));
    return r;
}
__device__ __forceinline__ uint32_t ex2h2(uint32_t s) {
    uint32_t r;
    asm("ex2.approx.f16x2 %0, %1;" : "=r"(r) : "r"(s));
    return r;
}
__device__ __forceinline__ uint32_t hadd2(uint32_t a, uint32_t b) {
    uint32_t r;
    asm("add.rn.f16x2 %0, %1, %2;" : "=r"(r) : "r"(a), "r"(b));
    return r;
}
__device__ __forceinline__ float2 h2f2(uint32_t v) {
    __half2 h = *(__half2*)&v;
    return __half22float2(h);
}
__device__ __forceinline__ uint32_t smem_u32(const void* p) {
    uint32_t a;
    asm("{ .reg .u64 t; cvta.to.shared.u64 t, %1; cvt.u32.u64 %0, t; }" : "=r"(a) : "l"(p));
    return a;
}
__device__ __forceinline__ void mma_f16(float* d, const uint32_t* a, uint32_t b0, uint32_t b1) {
    asm volatile(
        "mma.sync.aligned.m16n8k16.row.col.f32.f16.f16.f32 "
        "{%0,%1,%2,%3}, {%4,%5,%6,%7}, {%8,%9}, {%0,%1,%2,%3};"
        : "+f"(d[0]), "+f"(d[1]), "+f"(d[2]), "+f"(d[3])
        : "r"(a[0]), "r"(a[1]), "r"(a[2]), "r"(a[3]), "r"(b0), "r"(b1));
}
__device__ __forceinline__ void ldsm4(uint32_t* r, uint32_t a) {
    asm volatile("ldmatrix.sync.aligned.m8n8.x4.shared.b16 {%0,%1,%2,%3}, [%4];"
        : "=r"(r[0]), "=r"(r[1]), "=r"(r[2]), "=r"(r[3]) : "r"(a));
}
__device__ __forceinline__ void ldsm4t(uint32_t* r, uint32_t a) {
    asm volatile("ldmatrix.sync.aligned.m8n8.x4.trans.shared.b16 {%0,%1,%2,%3}, [%4];"
        : "=r"(r[0]), "=r"(r[1]), "=r"(r[2]), "=r"(r[3]) : "r"(a));
}
__device__ __forceinline__ void cpa16(uint32_t dst, const void* src) {
    asm volatile("cp.async.cg.shared.global [%0], [%1], 16;" :: "r"(dst), "l"(src) : "memory");
}
#define CP_COMMIT() asm volatile("cp.async.commit_group;" ::: "memory")
#define CP_WAIT0()  asm volatile("cp.async.wait_group 0;" ::: "memory")

// ======================= conversion prologues ==============================
__global__ void __launch_bounds__(256) conv_x_kernel(const float* __restrict__ x)
{
    int idx = blockIdx.x * 256 + threadIdx.x;
    int r = idx >> 6;
    int c8 = (idx & 63) * 8;
    const float4 v0 = *(const float4*)&x[(size_t)r * EMB + c8];
    const float4 v1 = *(const float4*)&x[(size_t)r * EMB + c8 + 4];
    uint4 o;
    o.x = packh2(v0.x, v0.y); o.y = packh2(v0.z, v0.w);
    o.z = packh2(v1.x, v1.y); o.w = packh2(v1.z, v1.w);
    *(uint4*)&g_xh[(size_t)r * HALF + c8] = o;
}

__global__ void __launch_bounds__(256) conv_w_kernel(
    const float* __restrict__ Wq, const float* __restrict__ Wk,
    const float* __restrict__ Wv, const float* __restrict__ Wo)
{
    int idx = blockIdx.x * 256 + threadIdx.x;
    int r = idx >> 6;
    int c8 = (idx & 63) * 8;
    const float* src;
    if (r < 512)       src = Wq + (size_t)r * HALF;
    else if (r < 1024) src = Wk + (size_t)(r - 512) * HALF;
    else if (r < 1536) src = Wv + (size_t)(r - 1024) * HALF;
    else               src = Wo + (size_t)(r - 1536) * HALF;
    const float4 v0 = *(const float4*)&src[c8];
    const float4 v1 = *(const float4*)&src[c8 + 4];
    uint4 o;
    o.x = packh2(v0.x, v0.y); o.y = packh2(v0.z, v0.w);
    o.z = packh2(v1.x, v1.y); o.w = packh2(v1.z, v1.w);
    *(uint4*)&g_wh[(size_t)r * HALF + c8] = o;
}

// ======================= f16 GEMM (unchanged) ==============================
template <int MODE>
__device__ __forceinline__ void gemm_h(
    const __half* __restrict__ Ag, const __half* __restrict__ Bg,
    void* __restrict__ Cout, int ldc, const float* __restrict__ bias, float scale)
{
    __shared__ __align__(16) uint8_t sA[2][8192];
    __shared__ __align__(16) uint8_t sB[2][4096];

    const int t = threadIdx.x;
    const int lane = t & 31;
    const int w = t >> 5;
    const int wm = (w & 3) * 32;
    const int wn = (w >> 2) * 32;
    const int g = lane >> 2;
    const int c = lane & 3;
    const int grp = lane >> 3;
    const int m0 = blockIdx.x * 128;
    const int n0 = blockIdx.y * 64;

    const int arow0 = (lane & 7) + 8 * (grp & 1);
    const int ajb = grp >> 1;
    const int asw = (arow0 >> 1) & 3;
    const int brow0 = (lane & 7) + 8 * (grp >> 1);
    const int bjb = grp & 1;
    const int bsw = (brow0 >> 1) & 3;

    const int ar[2] = {t >> 2, (t + 256) >> 2};
    const int ac = t & 3;
    const int br = t >> 2;

    uint4 pa[2], pb;
#pragma unroll
    for (int i = 0; i < 2; i++)
        pa[i] = *(const uint4*)((const uint8_t*)Ag + (size_t)(m0 + ar[i]) * 1024 + ac * 16);
    pb = *(const uint4*)((const uint8_t*)Bg + (size_t)(n0 + br) * 1024 + ac * 16);

    {
#pragma unroll
        for (int i = 0; i < 2; i++)
            *(uint4*)(sA[0] + ar[i] * 64 + ((ac ^ ((ar[i] >> 1) & 3)) << 4)) = pa[i];
        *(uint4*)(sB[0] + br * 64 + ((ac ^ ((br >> 1) & 3)) << 4)) = pb;
    }

    float acc[2][4][4] = {};

#pragma unroll 1
    for (int i = 0; i < 16; i++) {
        __syncthreads();
        const int b = i & 1;
        if (i < 15) {
            const int k0 = (i + 1) * 32;
#pragma unroll
            for (int j = 0; j < 2; j++)
                pa[j] = *(const uint4*)((const uint8_t*)Ag + (size_t)(m0 + ar[j]) * 1024 + k0 * 2 + ac * 16);
            pb = *(const uint4*)((const uint8_t*)Bg + (size_t)(n0 + br) * 1024 + k0 * 2 + ac * 16);
        }
        const uint32_t abase = smem_u32(sA[b]);
        const uint32_t bbase = smem_u32(sB[b]);
#pragma unroll
        for (int kc = 0; kc < 2; kc++) {
            uint32_t av[2][4], bv[2][4];
#pragma unroll
            for (int mt = 0; mt < 2; mt++)
                ldsm4(av[mt], abase + (wm + mt * 16 + arow0) * 64 + (((2 * kc + ajb) ^ asw) << 4));
#pragma unroll
            for (int np = 0; np < 2; np++)
                ldsm4(bv[np], bbase + (wn + np * 16 + brow0) * 64 + (((2 * kc + bjb) ^ bsw) << 4));
#pragma unroll
            for (int mt = 0; mt < 2; mt++)
#pragma unroll
                for (int np = 0; np < 2; np++) {
                    mma_f16(acc[mt][2 * np], av[mt], bv[np][0], bv[np][1]);
                    mma_f16(acc[mt][2 * np + 1], av[mt], bv[np][2], bv[np][3]);
                }
        }
        if (i < 15) {
            uint8_t* dA = sA[b ^ 1];
            uint8_t* dB = sB[b ^ 1];
#pragma unroll
            for (int j = 0; j < 2; j++)
                *(uint4*)(dA + ar[j] * 64 + ((ac ^ ((ar[j] >> 1) & 3)) << 4)) = pa[j];
            *(uint4*)(dB + br * 64 + ((ac ^ ((br >> 1) & 3)) << 4)) = pb;
        }
    }

#pragma unroll
    for (int mt = 0; mt < 2; mt++) {
        const int r0 = m0 + wm + mt * 16 + g;
#pragma unroll
        for (int np = 0; np < 2; np++)
#pragma unroll
            for (int hf = 0; hf < 2; hf++) {
                const int col = n0 + wn + np * 16 + hf * 8 + 2 * c;
                const float* a = acc[mt][2 * np + hf];
                if (MODE == 3) {
                    float* C = (float*)Cout;
                    const float b0 = bias[col], b1 = bias[col + 1];
                    *(float2*)&C[(size_t)r0 * ldc + col] = make_float2(a[0] + b0, a[1] + b1);
                    *(float2*)&C[(size_t)(r0 + 8) * ldc + col] = make_float2(a[2] + b0, a[3] + b1);
                } else {
                    uint32_t* C = (uint32_t*)Cout;
                    C[(size_t)r0 * (ldc / 2) + col / 2] = packh2(a[0] * scale, a[1] * scale);
                    C[(size_t)(r0 + 8) * (ldc / 2) + col / 2] = packh2(a[2] * scale, a[3] * scale);
                }
            }
    }
}

__global__ void __launch_bounds__(256) qkv_h_kernel()
{
    const int z = blockIdx.z;
    const float QS = 0.125f * 1.4426950408889634f;
    const __half* B = g_wh + (size_t)z * 512 * HALF;
    void* C = (z == 0) ? (void*)g_qh : (z == 1) ? (void*)g_kh : (void*)g_vh;
    gemm_h<0>(g_xh, B, C, HALF, nullptr, (z == 0) ? QS : 1.0f);
}

__global__ void __launch_bounds__(256) proj_h_kernel(
    const float* __restrict__ bo, float* __restrict__ out)
{
    gemm_h<3>(g_ath, g_wh + (size_t)1536 * HALF, out, EMB, bo, 1.0f);
}

// ======================= flash attention (split-K=4, cp.async) =============
// CTA = 128 q x 1 head x 1 key-split, 128 thr (4 warps x 32 q).
// 128-key smem tiles, inner 16-key chunks. l via HADD2 tree (off tensor pipe):
// per-tile f16x2 accumulators -> fp32 per tile -> quad shfl reduce at end.
__global__ void __launch_bounds__(128, 5) attn_kernel()
{
    __shared__ __align__(16) uint8_t sK[2][8192];
    __shared__ __align__(16) uint8_t sV[2][8192];

    const int t = threadIdx.x;
    const int lane = t & 31;
    const int w = t >> 5;
    const int g = lane >> 2;
    const int c = lane & 3;
    const int grp = lane >> 3;
    const int h = blockIdx.y;
    const int z = blockIdx.z;
    const int q0 = blockIdx.x * 128 + w * 32;
    const size_t kb0 = (size_t)z * KEYS_PER_SPLIT;

    const int krow0 = (lane & 7) + 8 * (grp >> 1);
    const int kjb = grp & 1;
    const int ksw = (krow0 >> 1) & 3;
    const int vrow0 = (lane & 7) + 8 * (grp & 1);
    const int vjb = grp >> 1;
    const int vsw = (vrow0 >> 1) & 3;

    // Q fragments, two m-tiles (scale folded in)
    uint32_t qa[2][2][4];
#pragma unroll
    for (int mt = 0; mt < 2; mt++) {
        const uint32_t* r0p = (const uint32_t*)g_qh + (size_t)(q0 + mt * 16 + g) * 256 + h * 16;
        const uint32_t* r8p = r0p + 8 * 256;
#pragma unroll
        for (int kc = 0; kc < 2; kc++) {
            qa[mt][kc][0] = r0p[8 * kc + c];
            qa[mt][kc][1] = r8p[8 * kc + c];
            qa[mt][kc][2] = r0p[8 * kc + c + 4];
            qa[mt][kc][3] = r8p[8 * kc + c + 4];
        }
    }

    float o[2][4][4] = {};
    float lf[2][2] = {};     // fp32 per-lane l partials [mt][row g / g+8]

    const uint8_t* Kh = (const uint8_t*)(g_kh + h * DH);
    const uint8_t* Vh = (const uint8_t*)(g_vh + h * DH);

    // cp.async loader: 512 16B-slots per matrix (128 rows x 4), 4 per thread
    const uint32_t skb[2] = {smem_u32(sK[0]), smem_u32(sK[1])};
    const uint32_t svb[2] = {smem_u32(sV[0]), smem_u32(sV[1])};
    int soff[4], goff[4];
#pragma unroll
    for (int i = 0; i < 4; i++) {
        const int slot = t + i * 128;
        const int r = slot >> 2, cc = slot & 3;
        soff[i] = r * 64 + ((cc ^ ((r >> 1) & 3)) << 4);
        goff[i] = r * 1024 + cc * 16;
    }

    // issue tile 0
#pragma unroll
    for (int i = 0; i < 4; i++) {
        cpa16(skb[0] + soff[i], Kh + kb0 * 1024 + goff[i]);
        cpa16(svb[0] + soff[i], Vh + kb0 * 1024 + goff[i]);
    }
    CP_COMMIT();

    const int NT = KEYS_PER_SPLIT / 128;
#pragma unroll 1
    for (int ti = 0; ti < NT; ti++) {
        const int b = ti & 1;
        CP_WAIT0();
        __syncthreads();
        if (ti + 1 < NT) {
            const size_t base = (kb0 + (size_t)(ti + 1) * 128) * 1024;
#pragma unroll
            for (int i = 0; i < 4; i++) {
                cpa16(skb[b ^ 1] + soff[i], Kh + base + goff[i]);
                cpa16(svb[b ^ 1] + soff[i], Vh + base + goff[i]);
            }
            CP_COMMIT();
        }

        const uint32_t kbase = skb[b];
        const uint32_t vbase = svb[b];

        uint32_t lh[2][2] = {{0u, 0u}, {0u, 0u}};  // per-tile f16x2 l accums

        // 8 chunks of 16 keys: S -> P -> PV
#pragma unroll
        for (int kk = 0; kk < 8; kk++) {
            const int roff = kk * 16;
            uint32_t kv0[4], kv1[4];
            const uint32_t krow = kbase + (roff + krow0) * 64;
            ldsm4(kv0, krow + (((0 + kjb) ^ ksw) << 4));
            ldsm4(kv1, krow + (((2 + kjb) ^ ksw) << 4));

            float s[2][2][4] = {};
#pragma unroll
            for (int mt = 0; mt < 2; mt++) {
                mma_f16(s[mt][0], qa[mt][0], kv0[0], kv0[1]);
                mma_f16(s[mt][1], qa[mt][0], kv0[2], kv0[3]);
                mma_f16(s[mt][0], qa[mt][1], kv1[0], kv1[1]);
                mma_f16(s[mt][1], qa[mt][1], kv1[2], kv1[3]);
            }

            uint32_t v0[4], v1[4];
            const uint32_t vrow = vbase + (roff + vrow0) * 64;
            ldsm4t(v0, vrow + (((0 + vjb) ^ vsw) << 4));
            ldsm4t(v1, vrow + (((2 + vjb) ^ vsw) << 4));

#pragma unroll
            for (int mt = 0; mt < 2; mt++) {
                uint32_t a[4];
                a[0] = ex2h2(packh2(s[mt][0][0], s[mt][0][1]));   // row g,   cols 2c,2c+1
                a[1] = ex2h2(packh2(s[mt][0][2], s[mt][0][3]));   // row g+8, cols 2c,2c+1
                a[2] = ex2h2(packh2(s[mt][1][0], s[mt][1][1]));   // row g,   cols 2c+8,2c+9
                a[3] = ex2h2(packh2(s[mt][1][2], s[mt][1][3]));   // row g+8, cols 2c+8,2c+9
                // l accumulation off the tensor pipe
                lh[mt][0] = hadd2(lh[mt][0], hadd2(a[0], a[2]));  // row g
                lh[mt][1] = hadd2(lh[mt][1], hadd2(a[1], a[3]));  // row g+8
                mma_f16(o[mt][0], a, v0[0], v0[1]);
                mma_f16(o[mt][1], a, v0[2], v0[3]);
                mma_f16(o[mt][2], a, v1[0], v1[1]);
                mma_f16(o[mt][3], a, v1[2], v1[3]);
            }
        }

        // flush per-tile f16x2 accumulators to fp32
#pragma unroll
        for (int mt = 0; mt < 2; mt++) {
            float2 f0 = h2f2(lh[mt][0]);
            float2 f1 = h2f2(lh[mt][1]);
            lf[mt][0] += f0.x + f0.y;
            lf[mt][1] += f1.x + f1.y;
        }
    }

    // quad reduce l (cols split across c lanes)
#pragma unroll
    for (int mt = 0; mt < 2; mt++) {
#pragma unroll
        for (int rr = 0; rr < 2; rr++) {
            lf[mt][rr] += __shfl_xor_sync(0xffffffffu, lf[mt][rr], 1);
            lf[mt][rr] += __shfl_xor_sync(0xffffffffu, lf[mt][rr], 2);
        }
    }

    // write fp32 partials (unnormalized)
    float* po = g_po[z];
    float* pl = g_pl[z];
#pragma unroll
    for (int mt = 0; mt < 2; mt++) {
        const int r0 = q0 + mt * 16 + g;
#pragma unroll
        for (int nt = 0; nt < 4; nt++) {
            const int col = h * DH + nt * 8 + 2 * c;
            *(float2*)&po[(size_t)r0 * HALF + col] = make_float2(o[mt][nt][0], o[mt][nt][1]);
            *(float2*)&po[(size_t)(r0 + 8) * HALF + col] = make_float2(o[mt][nt][2], o[mt][nt][3]);
        }
        if (c == 0) {
            pl[(size_t)r0 * NHEAD + h] = lf[mt][0];
            pl[(size_t)(r0 + 8) * NHEAD + h] = lf[mt][1];
        }
    }
}

// ======================= split-K reduce ====================================
__global__ void __launch_bounds__(256) attn_reduce_kernel()
{
    const int idx = blockIdx.x * 256 + threadIdx.x;  // 262144 total
    const int rh = idx >> 2;
    const int part = idx & 3;
    const int r = rh >> 4;
    const int h = rh & 15;

    float l = 0.0f;
#pragma unroll
    for (int z = 0; z < SPLIT; z++)
        l += g_pl[z][(size_t)r * NHEAD + h];
    const float inv = 1.0f / l;
    const size_t base = (size_t)r * HALF + h * DH + part * 8;

    float4 s0 = make_float4(0.f, 0.f, 0.f, 0.f);
    float4 s1 = make_float4(0.f, 0.f, 0.f, 0.f);
#pragma unroll
    for (int z = 0; z < SPLIT; z++) {
        const float4 a0 = *(const float4*)&g_po[z][base];
        const float4 a1 = *(const float4*)&g_po[z][base + 4];
        s0.x += a0.x; s0.y += a0.y; s0.z += a0.z; s0.w += a0.w;
        s1.x += a1.x; s1.y += a1.y; s1.z += a1.z; s1.w += a1.w;
    }

    uint4 o;
    o.x = packh2(s0.x * inv, s0.y * inv);
    o.y = packh2(s0.z * inv, s0.w * inv);
    o.z = packh2(s1.x * inv, s1.y * inv);
    o.w = packh2(s1.z * inv, s1.w * inv);
    *(uint4*)((uint32_t*)g_ath + (size_t)r * 256 + h * 16 + part * 4) = o;
}

extern "C" void kernel_launch(void* const* d_in, const int* in_sizes, int n_in,
                              void* d_out, int out_size)
{
    const float* x  = (const float*)d_in[0];
    const float* Wq = (const float*)d_in[1];
    const float* Wk = (const float*)d_in[2];
    const float* Wv = (const float*)d_in[3];
    const float* Wo = (const float*)d_in[4];
    const float* bo = (const float*)d_in[5];
    float* out = (float*)d_out;

    conv_x_kernel<<<1024, 256>>>(x);
    conv_w_kernel<<<640, 256>>>(Wq, Wk, Wv, Wo);

    dim3 gq(S_LEN / 128, HALF / 64, 3);
    qkv_h_kernel<<<gq, 256>>>();

    dim3 ga(S_LEN / 128, NHEAD, SPLIT);
    attn_kernel<<<ga, 128>>>();

    attn_reduce_kernel<<<1024, 256>>>();

    dim3 gp(S_LEN / 128, EMB / 64);
    proj_h_kernel<<<gp, 256>>>(bo, out);
}

// round 12
// speedup vs baseline: 1.1301x; 1.1301x over previous
#include <cuda_runtime.h>
#include <cuda_fp16.h>
#include <cstdint>

#define S_LEN 4096
#define EMB   1024
#define HALF  512
#define NHEAD 16
#define DH    32
#define SPLIT 2
#define KEYS_PER_SPLIT (S_LEN / SPLIT)

// f16 scratch
__device__ __half g_xh [S_LEN * HALF];   // x left half
__device__ __half g_wh [2560 * HALF];    // Wq|Wk|Wv|Wo rows (k-major)
__device__ __half g_qh [S_LEN * HALF];   // Q (scale*log2e folded in)
__device__ __half g_kh [S_LEN * HALF];
__device__ __half g_vh [S_LEN * HALF];
__device__ __half g_ath[S_LEN * HALF];   // attention output (f16)

// split-K partials (fp32)
__device__ float g_po[SPLIT][S_LEN * HALF];
__device__ float g_pl[SPLIT][S_LEN * NHEAD];

__device__ __forceinline__ uint32_t packh2(float lo, float hi) {
    uint32_t r;
    asm("cvt.rn.f16x2.f32 %0, %1, %2;" : "=r"(r) : "f"(hi), "f"(lo));
    return r;
}
__device__ __forceinline__ uint32_t ex2h2(uint32_t s) {
    uint32_t r;
    asm("ex2.approx.f16x2 %0, %1;" : "=r"(r) : "r"(s));
    return r;
}
__device__ __forceinline__ uint32_t smem_u32(const void* p) {
    uint32_t a;
    asm("{ .reg .u64 t; cvta.to.shared.u64 t, %1; cvt.u32.u64 %0, t; }" : "=r"(a) : "l"(p));
    return a;
}
__device__ __forceinline__ void mma_f16(float* d, const uint32_t* a, uint32_t b0, uint32_t b1) {
    asm volatile(
        "mma.sync.aligned.m16n8k16.row.col.f32.f16.f16.f32 "
        "{%0,%1,%2,%3}, {%4,%5,%6,%7}, {%8,%9}, {%0,%1,%2,%3};"
        : "+f"(d[0]), "+f"(d[1]), "+f"(d[2]), "+f"(d[3])
        : "r"(a[0]), "r"(a[1]), "r"(a[2]), "r"(a[3]), "r"(b0), "r"(b1));
}
__device__ __forceinline__ void ldsm4(uint32_t* r, uint32_t a) {
    asm volatile("ldmatrix.sync.aligned.m8n8.x4.shared.b16 {%0,%1,%2,%3}, [%4];"
        : "=r"(r[0]), "=r"(r[1]), "=r"(r[2]), "=r"(r[3]) : "r"(a));
}
__device__ __forceinline__ void ldsm4t(uint32_t* r, uint32_t a) {
    asm volatile("ldmatrix.sync.aligned.m8n8.x4.trans.shared.b16 {%0,%1,%2,%3}, [%4];"
        : "=r"(r[0]), "=r"(r[1]), "=r"(r[2]), "=r"(r[3]) : "r"(a));
}
__device__ __forceinline__ void cpa16(uint32_t dst, const void* src) {
    asm volatile("cp.async.cg.shared.global [%0], [%1], 16;" :: "r"(dst), "l"(src) : "memory");
}
#define CP_COMMIT() asm volatile("cp.async.commit_group;" ::: "memory")
#define CP_WAIT0()  asm volatile("cp.async.wait_group 0;" ::: "memory")

// ======================= merged conversion prologue ========================
// rows 0..4095: x left half -> g_xh ; rows 4096..6655: W rows -> g_wh
__global__ void __launch_bounds__(256) conv_all_kernel(
    const float* __restrict__ x,
    const float* __restrict__ Wq, const float* __restrict__ Wk,
    const float* __restrict__ Wv, const float* __restrict__ Wo)
{
    int idx = blockIdx.x * 256 + threadIdx.x;   // 0..425983
    int r = idx >> 6;
    int c8 = (idx & 63) * 8;
    const float* src;
    __half* dst;
    if (r < 4096) {
        src = x + (size_t)r * EMB;
        dst = g_xh + (size_t)r * HALF;
    } else {
        int wr = r - 4096;
        if (wr < 512)       src = Wq + (size_t)wr * HALF;
        else if (wr < 1024) src = Wk + (size_t)(wr - 512) * HALF;
        else if (wr < 1536) src = Wv + (size_t)(wr - 1024) * HALF;
        else                src = Wo + (size_t)(wr - 1536) * HALF;
        dst = g_wh + (size_t)wr * HALF;
    }
    const float4 v0 = *(const float4*)&src[c8];
    const float4 v1 = *(const float4*)&src[c8 + 4];
    uint4 o;
    o.x = packh2(v0.x, v0.y); o.y = packh2(v0.z, v0.w);
    o.z = packh2(v1.x, v1.y); o.w = packh2(v1.z, v1.w);
    *(uint4*)&dst[c8] = o;
}

// ======================= f16 GEMM, CTA 128x128 =============================
// C[m][n] = sum_k A[m][k]*B[n][k]. BK=32, 256 thr (8 warps), warp tile 32x64.
// Swizzled 64B smem rows, ldmatrix frags, double-buffered.
// MODE 0: half2 out (scaled). MODE 3: float out + bias.
template <int MODE>
__device__ __forceinline__ void gemm_h(
    const __half* __restrict__ Ag, const __half* __restrict__ Bg,
    void* __restrict__ Cout, int ldc, const float* __restrict__ bias, float scale)
{
    __shared__ __align__(16) uint8_t sA[2][8192];
    __shared__ __align__(16) uint8_t sB[2][8192];

    const int t = threadIdx.x;
    const int lane = t & 31;
    const int w = t >> 5;
    const int wm = (w & 3) * 32;
    const int wn = (w >> 2) * 64;
    const int g = lane >> 2;
    const int c = lane & 3;
    const int grp = lane >> 3;
    const int m0 = blockIdx.x * 128;
    const int n0 = blockIdx.y * 128;

    const int arow0 = (lane & 7) + 8 * (grp & 1);
    const int ajb = grp >> 1;
    const int asw = (arow0 >> 1) & 3;
    const int brow0 = (lane & 7) + 8 * (grp >> 1);
    const int bjb = grp & 1;
    const int bsw = (brow0 >> 1) & 3;

    // loaders: 512 16B-slots per matrix (128 rows x 4 chunks), 2 per thread
    const int lr[2] = {t >> 2, (t + 256) >> 2};
    const int ac = t & 3;

    uint4 pa[2], pb[2];
#pragma unroll
    for (int i = 0; i < 2; i++) {
        pa[i] = *(const uint4*)((const uint8_t*)Ag + (size_t)(m0 + lr[i]) * 1024 + ac * 16);
        pb[i] = *(const uint4*)((const uint8_t*)Bg + (size_t)(n0 + lr[i]) * 1024 + ac * 16);
    }
    {
#pragma unroll
        for (int i = 0; i < 2; i++) {
            const int off = lr[i] * 64 + ((ac ^ ((lr[i] >> 1) & 3)) << 4);
            *(uint4*)(sA[0] + off) = pa[i];
            *(uint4*)(sB[0] + off) = pb[i];
        }
    }

    float acc[2][8][4] = {};

#pragma unroll 1
    for (int i = 0; i < 16; i++) {
        __syncthreads();
        const int b = i & 1;
        if (i < 15) {
            const int k0 = (i + 1) * 32;
#pragma unroll
            for (int j = 0; j < 2; j++) {
                pa[j] = *(const uint4*)((const uint8_t*)Ag + (size_t)(m0 + lr[j]) * 1024 + k0 * 2 + ac * 16);
                pb[j] = *(const uint4*)((const uint8_t*)Bg + (size_t)(n0 + lr[j]) * 1024 + k0 * 2 + ac * 16);
            }
        }
        const uint32_t abase = smem_u32(sA[b]);
        const uint32_t bbase = smem_u32(sB[b]);
#pragma unroll
        for (int kc = 0; kc < 2; kc++) {
            uint32_t av[2][4], bv[4][4];
#pragma unroll
            for (int mt = 0; mt < 2; mt++)
                ldsm4(av[mt], abase + (wm + mt * 16 + arow0) * 64 + (((2 * kc + ajb) ^ asw) << 4));
#pragma unroll
            for (int np = 0; np < 4; np++)
                ldsm4(bv[np], bbase + (wn + np * 16 + brow0) * 64 + (((2 * kc + bjb) ^ bsw) << 4));
#pragma unroll
            for (int mt = 0; mt < 2; mt++)
#pragma unroll
                for (int np = 0; np < 4; np++) {
                    mma_f16(acc[mt][2 * np], av[mt], bv[np][0], bv[np][1]);
                    mma_f16(acc[mt][2 * np + 1], av[mt], bv[np][2], bv[np][3]);
                }
        }
        if (i < 15) {
            uint8_t* dA = sA[b ^ 1];
            uint8_t* dB = sB[b ^ 1];
#pragma unroll
            for (int j = 0; j < 2; j++) {
                const int off = lr[j] * 64 + ((ac ^ ((lr[j] >> 1) & 3)) << 4);
                *(uint4*)(dA + off) = pa[j];
                *(uint4*)(dB + off) = pb[j];
            }
        }
    }

#pragma unroll
    for (int mt = 0; mt < 2; mt++) {
        const int r0 = m0 + wm + mt * 16 + g;
#pragma unroll
        for (int nt = 0; nt < 8; nt++) {
            const int col = n0 + wn + nt * 8 + 2 * c;
            const float* a = acc[mt][nt];
            if (MODE == 3) {
                float* C = (float*)Cout;
                const float b0 = bias[col], b1 = bias[col + 1];
                *(float2*)&C[(size_t)r0 * ldc + col] = make_float2(a[0] + b0, a[1] + b1);
                *(float2*)&C[(size_t)(r0 + 8) * ldc + col] = make_float2(a[2] + b0, a[3] + b1);
            } else {
                uint32_t* C = (uint32_t*)Cout;
                C[(size_t)r0 * (ldc / 2) + col / 2] = packh2(a[0] * scale, a[1] * scale);
                C[(size_t)(r0 + 8) * (ldc / 2) + col / 2] = packh2(a[2] * scale, a[3] * scale);
            }
        }
    }
}

__global__ void __launch_bounds__(256, 2) qkv_h_kernel()
{
    const int z = blockIdx.z;
    const float QS = 0.125f * 1.4426950408889634f;
    const __half* B = g_wh + (size_t)z * 512 * HALF;
    void* C = (z == 0) ? (void*)g_qh : (z == 1) ? (void*)g_kh : (void*)g_vh;
    gemm_h<0>(g_xh, B, C, HALF, nullptr, (z == 0) ? QS : 1.0f);
}

__global__ void __launch_bounds__(256, 2) proj_h_kernel(
    const float* __restrict__ bo, float* __restrict__ out)
{
    gemm_h<3>(g_ath, g_wh + (size_t)1536 * HALF, out, EMB, bo, 1.0f);
}

// ======================= flash attention (split-K=2, cp.async) =============
// CTA = 128 q x 1 head x 1 key-split, 128 thr (4 warps x 32 q).
// 128-key smem tiles via cp.async double-buffering; inner 16-key chunks.
// Partial O (unnormalized, fp32) + l written to g_po/g_pl; reduce fuses.
__global__ void __launch_bounds__(128, 5) attn_kernel()
{
    __shared__ __align__(16) uint8_t sK[2][8192];
    __shared__ __align__(16) uint8_t sV[2][8192];

    const int t = threadIdx.x;
    const int lane = t & 31;
    const int w = t >> 5;
    const int g = lane >> 2;
    const int c = lane & 3;
    const int grp = lane >> 3;
    const int h = blockIdx.y;
    const int z = blockIdx.z;
    const int q0 = blockIdx.x * 128 + w * 32;
    const size_t kb0 = (size_t)z * KEYS_PER_SPLIT;

    const int krow0 = (lane & 7) + 8 * (grp >> 1);
    const int kjb = grp & 1;
    const int ksw = (krow0 >> 1) & 3;
    const int vrow0 = (lane & 7) + 8 * (grp & 1);
    const int vjb = grp >> 1;
    const int vsw = (vrow0 >> 1) & 3;

    // Q fragments, two m-tiles (scale folded in)
    uint32_t qa[2][2][4];
#pragma unroll
    for (int mt = 0; mt < 2; mt++) {
        const uint32_t* r0p = (const uint32_t*)g_qh + (size_t)(q0 + mt * 16 + g) * 256 + h * 16;
        const uint32_t* r8p = r0p + 8 * 256;
#pragma unroll
        for (int kc = 0; kc < 2; kc++) {
            qa[mt][kc][0] = r0p[8 * kc + c];
            qa[mt][kc][1] = r8p[8 * kc + c];
            qa[mt][kc][2] = r0p[8 * kc + c + 4];
            qa[mt][kc][3] = r8p[8 * kc + c + 4];
        }
    }

    float o[2][4][4] = {};
    float lacc[2][4] = {};
    const uint32_t ONE2 = 0x3C003C00u;

    const uint8_t* Kh = (const uint8_t*)(g_kh + h * DH);
    const uint8_t* Vh = (const uint8_t*)(g_vh + h * DH);

    // cp.async loader: 512 16B-slots per matrix (128 rows x 4), 4 per thread
    const uint32_t skb[2] = {smem_u32(sK[0]), smem_u32(sK[1])};
    const uint32_t svb[2] = {smem_u32(sV[0]), smem_u32(sV[1])};
    int soff[4], goff[4];
#pragma unroll
    for (int i = 0; i < 4; i++) {
        const int slot = t + i * 128;
        const int r = slot >> 2, cc = slot & 3;
        soff[i] = r * 64 + ((cc ^ ((r >> 1) & 3)) << 4);
        goff[i] = r * 1024 + cc * 16;
    }

    // issue tile 0
#pragma unroll
    for (int i = 0; i < 4; i++) {
        cpa16(skb[0] + soff[i], Kh + kb0 * 1024 + goff[i]);
        cpa16(svb[0] + soff[i], Vh + kb0 * 1024 + goff[i]);
    }
    CP_COMMIT();

    const int NT = KEYS_PER_SPLIT / 128;
#pragma unroll 1
    for (int ti = 0; ti < NT; ti++) {
        const int b = ti & 1;
        CP_WAIT0();
        __syncthreads();
        if (ti + 1 < NT) {
            const size_t base = (kb0 + (size_t)(ti + 1) * 128) * 1024;
#pragma unroll
            for (int i = 0; i < 4; i++) {
                cpa16(skb[b ^ 1] + soff[i], Kh + base + goff[i]);
                cpa16(svb[b ^ 1] + soff[i], Vh + base + goff[i]);
            }
            CP_COMMIT();
        }

        const uint32_t kbase = skb[b];
        const uint32_t vbase = svb[b];

        // 8 chunks of 16 keys: S -> P -> PV
#pragma unroll
        for (int kk = 0; kk < 8; kk++) {
            const int roff = kk * 16;
            uint32_t kv0[4], kv1[4];
            const uint32_t krow = kbase + (roff + krow0) * 64;
            ldsm4(kv0, krow + (((0 + kjb) ^ ksw) << 4));
            ldsm4(kv1, krow + (((2 + kjb) ^ ksw) << 4));

            float s[2][2][4] = {};
#pragma unroll
            for (int mt = 0; mt < 2; mt++) {
                mma_f16(s[mt][0], qa[mt][0], kv0[0], kv0[1]);
                mma_f16(s[mt][1], qa[mt][0], kv0[2], kv0[3]);
                mma_f16(s[mt][0], qa[mt][1], kv1[0], kv1[1]);
                mma_f16(s[mt][1], qa[mt][1], kv1[2], kv1[3]);
            }

            uint32_t v0[4], v1[4];
            const uint32_t vrow = vbase + (roff + vrow0) * 64;
            ldsm4t(v0, vrow + (((0 + vjb) ^ vsw) << 4));
            ldsm4t(v1, vrow + (((2 + vjb) ^ vsw) << 4));

#pragma unroll
            for (int mt = 0; mt < 2; mt++) {
                uint32_t a[4];
                a[0] = ex2h2(packh2(s[mt][0][0], s[mt][0][1]));
                a[1] = ex2h2(packh2(s[mt][0][2], s[mt][0][3]));
                a[2] = ex2h2(packh2(s[mt][1][0], s[mt][1][1]));
                a[3] = ex2h2(packh2(s[mt][1][2], s[mt][1][3]));
                mma_f16(o[mt][0], a, v0[0], v0[1]);
                mma_f16(o[mt][1], a, v0[2], v0[3]);
                mma_f16(o[mt][2], a, v1[0], v1[1]);
                mma_f16(o[mt][3], a, v1[2], v1[3]);
                mma_f16(lacc[mt], a, ONE2, ONE2);
            }
        }
    }

    // write fp32 partials (unnormalized)
    float* po = g_po[z];
    float* pl = g_pl[z];
#pragma unroll
    for (int mt = 0; mt < 2; mt++) {
        const int r0 = q0 + mt * 16 + g;
#pragma unroll
        for (int nt = 0; nt < 4; nt++) {
            const int col = h * DH + nt * 8 + 2 * c;
            *(float2*)&po[(size_t)r0 * HALF + col] = make_float2(o[mt][nt][0], o[mt][nt][1]);
            *(float2*)&po[(size_t)(r0 + 8) * HALF + col] = make_float2(o[mt][nt][2], o[mt][nt][3]);
        }
        if (c == 0) {
            pl[(size_t)r0 * NHEAD + h] = lacc[mt][0];
            pl[(size_t)(r0 + 8) * NHEAD + h] = lacc[mt][2];
        }
    }
}

// ======================= split-K reduce ====================================
__global__ void __launch_bounds__(256) attn_reduce_kernel()
{
    const int idx = blockIdx.x * 256 + threadIdx.x;  // 262144 total
    const int rh = idx >> 2;
    const int part = idx & 3;
    const int r = rh >> 4;
    const int h = rh & 15;

    const float l = g_pl[0][(size_t)r * NHEAD + h] + g_pl[1][(size_t)r * NHEAD + h];
    const float inv = 1.0f / l;
    const size_t base = (size_t)r * HALF + h * DH + part * 8;

    const float4 a0 = *(const float4*)&g_po[0][base];
    const float4 a1 = *(const float4*)&g_po[0][base + 4];
    const float4 b0 = *(const float4*)&g_po[1][base];
    const float4 b1 = *(const float4*)&g_po[1][base + 4];

    uint4 o;
    o.x = packh2((a0.x + b0.x) * inv, (a0.y + b0.y) * inv);
    o.y = packh2((a0.z + b0.z) * inv, (a0.w + b0.w) * inv);
    o.z = packh2((a1.x + b1.x) * inv, (a1.y + b1.y) * inv);
    o.w = packh2((a1.z + b1.z) * inv, (a1.w + b1.w) * inv);
    *(uint4*)((uint32_t*)g_ath + (size_t)r * 256 + h * 16 + part * 4) = o;
}

extern "C" void kernel_launch(void* const* d_in, const int* in_sizes, int n_in,
                              void* d_out, int out_size)
{
    const float* x  = (const float*)d_in[0];
    const float* Wq = (const float*)d_in[1];
    const float* Wk = (const float*)d_in[2];
    const float* Wv = (const float*)d_in[3];
    const float* Wo = (const float*)d_in[4];
    const float* bo = (const float*)d_in[5];
    float* out = (float*)d_out;

    conv_all_kernel<<<1664, 256>>>(x, Wq, Wk, Wv, Wo);

    dim3 gq(S_LEN / 128, HALF / 128, 3);     // (32, 4, 3) = 384 CTAs
    qkv_h_kernel<<<gq, 256>>>();

    dim3 ga(S_LEN / 128, NHEAD, SPLIT);      // (32, 16, 2) = 1024 CTAs
    attn_kernel<<<ga, 128>>>();

    attn_reduce_kernel<<<1024, 256>>>();

    dim3 gp(S_LEN / 128, EMB / 128);         // (32, 8) = 256 CTAs
    proj_h_kernel<<<gp, 256>>>(bo, out);
}